// round 11
// baseline (speedup 1.0000x reference)
#include <cuda_runtime.h>
#include <cuda_bf16.h>
#include <cstdint>

#define N_NODES 50000
#define N_EDGES 600000
#define D 128

#define SCAN_BT 256
#define SCAN_NB ((N_NODES + SCAN_BT - 1) / SCAN_BT)   // 196

// GEMM tile config: 64 rows x 128 cols per block, 256 thr = 8 warps (4m x 2n)
#define GBM 64
#define GBN 128
#define NCHUNK 16                 // 256 K / 16 per chunk
#define ZROW_STRIDE 144           // floats; 36 float4-units -> conflict-free LDS.128

// Dynamic smem layout (32-bit words)
#define SM_ZROW_W (GBM * ZROW_STRIDE)          // 9216
#define SM_AH_W   (SM_ZROW_W)                  // +2*512
#define SM_AL_W   (SM_AH_W + 1024)
#define SM_BH_W   (SM_AL_W + 1024)             // +2*4*264
#define SM_BL_W   (SM_BH_W + 2112)
#define SM_TOTAL_W (SM_BL_W + 2112)            // 15488 words = 61952 B

// Scratch (__device__ globals; no allocation allowed)
__device__ int   g_cnt[N_NODES];     // zero at start of every call (fused kernel re-zeroes)
__device__ int   g_offs[N_NODES];
__device__ int   g_cursor[N_NODES];
__device__ int   g_bsum[SCAN_NB];
__device__ int   g_ssrc[N_EDGES];
__device__ float g_sw[N_EDGES];
// W pre-packed as bf16 hi/lo words in mma-fragment order:
// flat idx = chunk*1024 + tig*256 + n*2 + which;  word = {lo: W[n][kb], hi: W[n][kb+1]},
// kb = chunk*16 + tig*2 + which*8
__device__ __align__(16) uint32_t g_Wbh[NCHUNK * 1024];
__device__ __align__(16) uint32_t g_Wbl[NCHUNK * 1024];

// ---- index dtype detection (values < 50000; int64 LE => odd words zero) ----
__device__ __forceinline__ bool idx_is64(const int* p) {
    return ((p[1] | p[3] | p[5] | p[7]) == 0);
}
__device__ __forceinline__ int edge_idx(const int* p, bool is64, int e) {
    return is64 ? (int)((const long long*)p)[e] : p[e];
}

// ---- bf16 2-term split of a float pair, packed as bf16x2 words ----
__device__ __forceinline__ void splitpack2(float x0, float x1,
                                           uint32_t& h, uint32_t& l) {
    float h0 = __bfloat162float(__float2bfloat16_rn(x0));
    float h1 = __bfloat162float(__float2bfloat16_rn(x1));
    asm("cvt.rn.bf16x2.f32 %0, %1, %2;" : "=r"(h) : "f"(h1), "f"(h0));
    asm("cvt.rn.bf16x2.f32 %0, %1, %2;" : "=r"(l) : "f"(x1 - h1), "f"(x0 - h0));
}

// ---------------------------------------------------------------------------
// init: pack W into bf16 hi/lo fragment-order arrays (16384 threads)
// ---------------------------------------------------------------------------
__global__ void init_kernel(const float* __restrict__ W) {
    int idx = blockIdx.x * blockDim.x + threadIdx.x;
    if (idx < NCHUNK * 1024) {
        int chunk = idx >> 10;
        int ww    = idx & 1023;
        int tigr  = ww >> 8;
        int n     = (ww >> 1) & 127;
        int which = ww & 1;
        int kb    = chunk * 16 + tigr * 2 + which * 8;
        float x0 = W[n * 2 * D + kb];
        float x1 = W[n * 2 * D + kb + 1];
        uint32_t h, l;
        splitpack2(x0, x1, h, l);
        g_Wbh[idx] = h;
        g_Wbl[idx] = l;
    }
}

__global__ void hist_kernel(const int* __restrict__ dst) {
    int e = blockIdx.x * blockDim.x + threadIdx.x;
    if (e >= N_EDGES) return;
    bool is64 = idx_is64(dst);
    atomicAdd(&g_cnt[edge_idx(dst, is64, e)], 1);
}

// ---------------------------------------------------------------------------
// 2-pass exclusive scan of g_cnt[50000] -> g_offs / g_cursor
// ---------------------------------------------------------------------------
__global__ void scan_pass1() {
    __shared__ int sh[SCAN_BT];
    int t = threadIdx.x;
    int i = blockIdx.x * SCAN_BT + t;
    int v = (i < N_NODES) ? g_cnt[i] : 0;
    sh[t] = v;
    __syncthreads();
    #pragma unroll
    for (int off = 1; off < SCAN_BT; off <<= 1) {
        int u = (t >= off) ? sh[t - off] : 0;
        __syncthreads();
        sh[t] += u;
        __syncthreads();
    }
    if (i < N_NODES) g_offs[i] = sh[t] - v;
    if (t == SCAN_BT - 1) g_bsum[blockIdx.x] = sh[t];
}

__global__ void scan_pass23() {
    __shared__ int sh[SCAN_BT];
    int t = threadIdx.x;
    int v = (t < SCAN_NB) ? g_bsum[t] : 0;
    sh[t] = v;
    __syncthreads();
    #pragma unroll
    for (int off = 1; off < SCAN_BT; off <<= 1) {
        int u = (t >= off) ? sh[t - off] : 0;
        __syncthreads();
        sh[t] += u;
        __syncthreads();
    }
    int base = (blockIdx.x > 0) ? sh[blockIdx.x - 1] : 0;
    int i = blockIdx.x * SCAN_BT + t;
    if (i < N_NODES) {
        int o = g_offs[i] + base;
        g_offs[i] = o;
        g_cursor[i] = o;
    }
}

// ---------------------------------------------------------------------------
__global__ void scatter_ids_kernel(const float* __restrict__ ew,
                                   const int* __restrict__ src,
                                   const int* __restrict__ dst) {
    int e = blockIdx.x * blockDim.x + threadIdx.x;
    if (e >= N_EDGES) return;
    bool s64 = idx_is64(src);
    bool d64 = idx_is64(dst);
    int s = edge_idx(src, s64, e);
    int d = edge_idx(dst, d64, e);
    int pos = atomicAdd(&g_cursor[d], 1);
    g_ssrc[pos] = s;
    g_sw[pos] = ew[e];
}

// ---------------------------------------------------------------------------
// FUSED gather + bf16-split MMA GEMM.
// Phase 1: each warp gathers 8 of the block's 64 node rows into smem zrow
//          (fp32, normalized by degree), zeroing g_cnt for the next call.
// Phase 2: out[n][j] = sum_k z[n][k] * W[j][k] + b[j], with
//          z from smem (k<128) or nf (k>=128), double-buffered frag pipeline.
// ---------------------------------------------------------------------------
__device__ __forceinline__ void mma_bf16(float* c, const uint32_t* a,
                                         uint32_t b0, uint32_t b1) {
    asm volatile(
        "mma.sync.aligned.m16n8k16.row.col.f32.bf16.bf16.f32 "
        "{%0,%1,%2,%3}, {%4,%5,%6,%7}, {%8,%9}, {%0,%1,%2,%3};"
        : "+f"(c[0]), "+f"(c[1]), "+f"(c[2]), "+f"(c[3])
        : "r"(a[0]), "r"(a[1]), "r"(a[2]), "r"(a[3]), "r"(b0), "r"(b1));
}

__global__ __launch_bounds__(256)
void gemm_fused_kernel(const float* __restrict__ nf,
                       const float* __restrict__ bias,
                       float* __restrict__ out) {
    extern __shared__ __align__(16) uint32_t smem[];
    float*    zrow = (float*)smem;              // [64][ZROW_STRIDE]
    uint32_t* AhF  = smem + SM_AH_W;            // [2][512]
    uint32_t* AlF  = smem + SM_AL_W;
    uint32_t* BhF  = smem + SM_BH_W;            // [2][4][264]
    uint32_t* BlF  = smem + SM_BL_W;

    int tx   = threadIdx.x;
    int w    = tx >> 5;
    int lane = tx & 31;
    int g    = lane >> 2;
    int tig  = lane & 3;
    int mwg  = w >> 1;
    int nw   = (w & 1) * 64;
    int n0   = blockIdx.x * GBM;

    // ================= Phase 1: gather into zrow =================
    {
        const float4* nf4 = (const float4*)nf;
        #pragma unroll 1
        for (int r = 0; r < 8; r++) {
            int m = w * 8 + r;
            int node = n0 + m;
            float4 acc = make_float4(0.f, 0.f, 0.f, 0.f);
            if (node < N_NODES) {
                int beg = g_offs[node];
                int deg = g_cnt[node];
                int i = 0;
                for (; i + 4 <= deg; i += 4) {
                    int   s0 = g_ssrc[beg + i];
                    int   s1 = g_ssrc[beg + i + 1];
                    int   s2 = g_ssrc[beg + i + 2];
                    int   s3 = g_ssrc[beg + i + 3];
                    float w0 = g_sw[beg + i];
                    float w1 = g_sw[beg + i + 1];
                    float w2 = g_sw[beg + i + 2];
                    float w3 = g_sw[beg + i + 3];
                    float4 v0 = nf4[s0 * (D / 4) + lane];
                    float4 v1 = nf4[s1 * (D / 4) + lane];
                    float4 v2 = nf4[s2 * (D / 4) + lane];
                    float4 v3 = nf4[s3 * (D / 4) + lane];
                    acc.x += v0.x * w0; acc.y += v0.y * w0; acc.z += v0.z * w0; acc.w += v0.w * w0;
                    acc.x += v1.x * w1; acc.y += v1.y * w1; acc.z += v1.z * w1; acc.w += v1.w * w1;
                    acc.x += v2.x * w2; acc.y += v2.y * w2; acc.z += v2.z * w2; acc.w += v2.w * w2;
                    acc.x += v3.x * w3; acc.y += v3.y * w3; acc.z += v3.z * w3; acc.w += v3.w * w3;
                }
                for (; i < deg; i++) {
                    int s = g_ssrc[beg + i];
                    float wt = g_sw[beg + i];
                    float4 v = nf4[s * (D / 4) + lane];
                    acc.x += v.x * wt; acc.y += v.y * wt; acc.z += v.z * wt; acc.w += v.w * wt;
                }
                float inv = (deg > 0) ? (1.0f / (float)deg) : 0.0f;
                acc.x *= inv; acc.y *= inv; acc.z *= inv; acc.w *= inv;
                if (lane == 0) g_cnt[node] = 0;   // reset for next call
            }
            *(float4*)(zrow + m * ZROW_STRIDE + lane * 4) = acc;
        }
    }
    __syncthreads();

    // ================= Phase 2: GEMM =================
    float c[8][4];
    #pragma unroll
    for (int t = 0; t < 8; t++)
        #pragma unroll
        for (int i = 0; i < 4; i++) c[t][i] = 0.f;

    int am = tx >> 2;
    int aq = tx & 3;
    int anode = n0 + am;
    if (anode >= N_NODES) anode = 0;        // only used for nf (k>=128) reads
    int ar = am & 15, ag = ar & 7, ahalf = ar >> 3, amg = am >> 4;
    int i0 = 2 * aq, i1 = 2 * aq + 1;
    int ad0 = amg * 128 + (4 * ag + (i0 & 3)) * 4 + ahalf + 2 * (i0 >> 2);
    int ad1 = amg * 128 + (4 * ag + (i1 & 3)) * 4 + ahalf + 2 * (i1 >> 2);

    const uint2* Wh2 = (const uint2*)g_Wbh;
    const uint2* Wl2 = (const uint2*)g_Wbl;
    int t0row = tx >> 7;
    int t0off = (2 * tx) & 255;

    // prologue: chunk 0 (always from zrow)
    {
        float4 f = *(const float4*)(zrow + am * ZROW_STRIDE + aq * 4);
        uint32_t h0, l0, h1, l1;
        splitpack2(f.x, f.y, h0, l0);
        splitpack2(f.z, f.w, h1, l1);
        AhF[ad0] = h0; AlF[ad0] = l0;
        AhF[ad1] = h1; AlF[ad1] = l1;
        uint2 bh0 = Wh2[tx], bh1 = Wh2[tx + 256];
        uint2 bl0 = Wl2[tx], bl1 = Wl2[tx + 256];
        *(uint2*)&BhF[t0row * 264 + t0off]       = bh0;
        *(uint2*)&BhF[(t0row + 2) * 264 + t0off] = bh1;
        *(uint2*)&BlF[t0row * 264 + t0off]       = bl0;
        *(uint2*)&BlF[(t0row + 2) * 264 + t0off] = bl1;
    }
    __syncthreads();

    for (int kt = 0; kt < NCHUNK; kt++) {
        int b = kt & 1;

        float4 pf;
        uint2 ph0, ph1, pl0, pl1;
        if (kt + 1 < NCHUNK) {
            int k0 = (kt + 1) * 16;
            if (k0 < D) {
                pf = *(const float4*)(zrow + am * ZROW_STRIDE + k0 + aq * 4);
            } else {
                pf = *(const float4*)(nf + (long long)anode * D + (k0 - D) + aq * 4);
            }
            int cb = (kt + 1) * 512;
            ph0 = Wh2[cb + tx]; ph1 = Wh2[cb + tx + 256];
            pl0 = Wl2[cb + tx]; pl1 = Wl2[cb + tx + 256];
        }

        uint4 a4h = *(const uint4*)&AhF[b * 512 + mwg * 128 + lane * 4];
        uint4 a4l = *(const uint4*)&AlF[b * 512 + mwg * 128 + lane * 4];
        uint32_t ah[4] = {a4h.x, a4h.y, a4h.z, a4h.w};
        uint32_t al[4] = {a4l.x, a4l.y, a4l.z, a4l.w};
        #pragma unroll
        for (int t = 0; t < 8; t++) {
            int nn = nw + t * 8 + g;
            uint2 bh = *(const uint2*)&BhF[b * 1056 + tig * 264 + nn * 2];
            uint2 bl = *(const uint2*)&BlF[b * 1056 + tig * 264 + nn * 2];
            mma_bf16(c[t], ah, bh.x, bh.y);
            mma_bf16(c[t], al, bh.x, bh.y);
            mma_bf16(c[t], ah, bl.x, bl.y);
        }

        if (kt + 1 < NCHUNK) {
            int nb = b ^ 1;
            uint32_t h0, l0, h1, l1;
            splitpack2(pf.x, pf.y, h0, l0);
            splitpack2(pf.z, pf.w, h1, l1);
            AhF[nb * 512 + ad0] = h0; AlF[nb * 512 + ad0] = l0;
            AhF[nb * 512 + ad1] = h1; AlF[nb * 512 + ad1] = l1;
            *(uint2*)&BhF[nb * 1056 + t0row * 264 + t0off]       = ph0;
            *(uint2*)&BhF[nb * 1056 + (t0row + 2) * 264 + t0off] = ph1;
            *(uint2*)&BlF[nb * 1056 + t0row * 264 + t0off]       = pl0;
            *(uint2*)&BlF[nb * 1056 + (t0row + 2) * 264 + t0off] = pl1;
        }
        __syncthreads();
    }

    // epilogue: bias + store
    int r0 = n0 + mwg * 16 + g;
    int r1 = r0 + 8;
    #pragma unroll
    for (int t = 0; t < 8; t++) {
        int col = nw + t * 8 + 2 * tig;
        float2 bv = *(const float2*)(bias + col);
        if (r0 < N_NODES) {
            float2 o0 = make_float2(c[t][0] + bv.x, c[t][1] + bv.y);
            *(float2*)(out + (long long)r0 * GBN + col) = o0;
        }
        if (r1 < N_NODES) {
            float2 o1 = make_float2(c[t][2] + bv.x, c[t][3] + bv.y);
            *(float2*)(out + (long long)r1 * GBN + col) = o1;
        }
    }
}

// ---------------------------------------------------------------------------
extern "C" void kernel_launch(void* const* d_in, const int* in_sizes, int n_in,
                              void* d_out, int out_size) {
    const float* nf   = (const float*)d_in[0];
    const float* ew   = (const float*)d_in[1];
    const float* W    = (const float*)d_in[2];
    const float* bias = (const float*)d_in[3];
    const int* src    = (const int*)d_in[4];
    const int* dst    = (const int*)d_in[5];
    float* out        = (float*)d_out;

    static bool attr_set = false;
    if (!attr_set) {
        cudaFuncSetAttribute(gemm_fused_kernel,
                             cudaFuncAttributeMaxDynamicSharedMemorySize,
                             SM_TOTAL_W * 4);
        attr_set = true;
    }

    init_kernel<<<(NCHUNK * 1024 + 255) / 256, 256>>>(W);
    hist_kernel<<<(N_EDGES + 255) / 256, 256>>>(dst);
    scan_pass1<<<SCAN_NB, SCAN_BT>>>();
    scan_pass23<<<SCAN_NB, SCAN_BT>>>();
    scatter_ids_kernel<<<(N_EDGES + 255) / 256, 256>>>(ew, src, dst);
    gemm_fused_kernel<<<(N_NODES + GBM - 1) / GBM, 256, SM_TOTAL_W * 4>>>(nf, bias, out);
}

// round 12
// speedup vs baseline: 1.1598x; 1.1598x over previous
#include <cuda_runtime.h>
#include <cuda_bf16.h>
#include <cstdint>

#define N_NODES 50000
#define N_EDGES 600000
#define D 128

#define SCAN_BT 256
#define SCAN_NB ((N_NODES + SCAN_BT - 1) / SCAN_BT)   // 196

// GEMM tile: 128 rows x 128 cols per block, 256 thr = 8 warps (4 m-pairs x 2 n)
#define GBM 128
#define GBN 128
#define NCHUNK 16                 // 256 K / 16 per chunk

// Scratch (__device__ globals; no allocation allowed)
__device__ float g_agg[N_NODES * D];
__device__ int   g_cnt[N_NODES];     // zeroed by gather after use each call
__device__ int   g_offs[N_NODES];
__device__ int   g_cursor[N_NODES];
__device__ int   g_bsum[SCAN_NB];
__device__ int   g_ssrc[N_EDGES];
__device__ float g_sw[N_EDGES];
// W pre-packed as bf16 hi/lo words in mma-fragment order (same as R8-R10)
__device__ __align__(16) uint32_t g_Wbh[NCHUNK * 1024];
__device__ __align__(16) uint32_t g_Wbl[NCHUNK * 1024];

// ---- index dtype detection (values < 50000; int64 LE => odd words zero) ----
__device__ __forceinline__ bool idx_is64(const int* p) {
    return ((p[1] | p[3] | p[5] | p[7]) == 0);
}
__device__ __forceinline__ int edge_idx(const int* p, bool is64, int e) {
    return is64 ? (int)((const long long*)p)[e] : p[e];
}

// ---- bf16 2-term split of a float pair, packed as bf16x2 words ----
__device__ __forceinline__ void splitpack2(float x0, float x1,
                                           uint32_t& h, uint32_t& l) {
    float h0 = __bfloat162float(__float2bfloat16_rn(x0));
    float h1 = __bfloat162float(__float2bfloat16_rn(x1));
    asm("cvt.rn.bf16x2.f32 %0, %1, %2;" : "=r"(h) : "f"(h1), "f"(h0));
    asm("cvt.rn.bf16x2.f32 %0, %1, %2;" : "=r"(l) : "f"(x1 - h1), "f"(x0 - h0));
}

// ---------------------------------------------------------------------------
// Fused hist + W-pack (first 16384 threads also pack W)
// ---------------------------------------------------------------------------
__global__ void hist_init_kernel(const float* __restrict__ W,
                                 const int* __restrict__ dst) {
    int idx = blockIdx.x * blockDim.x + threadIdx.x;
    if (idx < NCHUNK * 1024) {
        int chunk = idx >> 10;
        int ww    = idx & 1023;
        int tigr  = ww >> 8;
        int n     = (ww >> 1) & 127;
        int which = ww & 1;
        int kb    = chunk * 16 + tigr * 2 + which * 8;
        float x0 = W[n * 2 * D + kb];
        float x1 = W[n * 2 * D + kb + 1];
        uint32_t h, l;
        splitpack2(x0, x1, h, l);
        g_Wbh[idx] = h;
        g_Wbl[idx] = l;
    }
    if (idx < N_EDGES) {
        bool is64 = idx_is64(dst);
        atomicAdd(&g_cnt[edge_idx(dst, is64, idx)], 1);
    }
}

// ---------------------------------------------------------------------------
// 2-pass exclusive scan of g_cnt[50000] -> g_offs / g_cursor
// ---------------------------------------------------------------------------
__global__ void scan_pass1() {
    __shared__ int sh[SCAN_BT];
    int t = threadIdx.x;
    int i = blockIdx.x * SCAN_BT + t;
    int v = (i < N_NODES) ? g_cnt[i] : 0;
    sh[t] = v;
    __syncthreads();
    #pragma unroll
    for (int off = 1; off < SCAN_BT; off <<= 1) {
        int u = (t >= off) ? sh[t - off] : 0;
        __syncthreads();
        sh[t] += u;
        __syncthreads();
    }
    if (i < N_NODES) g_offs[i] = sh[t] - v;
    if (t == SCAN_BT - 1) g_bsum[blockIdx.x] = sh[t];
}

__global__ void scan_pass23() {
    __shared__ int sh[SCAN_BT];
    int t = threadIdx.x;
    int v = (t < SCAN_NB) ? g_bsum[t] : 0;
    sh[t] = v;
    __syncthreads();
    #pragma unroll
    for (int off = 1; off < SCAN_BT; off <<= 1) {
        int u = (t >= off) ? sh[t - off] : 0;
        __syncthreads();
        sh[t] += u;
        __syncthreads();
    }
    int base = (blockIdx.x > 0) ? sh[blockIdx.x - 1] : 0;
    int i = blockIdx.x * SCAN_BT + t;
    if (i < N_NODES) {
        int o = g_offs[i] + base;
        g_offs[i] = o;
        g_cursor[i] = o;
    }
}

// ---------------------------------------------------------------------------
__global__ void scatter_ids_kernel(const float* __restrict__ ew,
                                   const int* __restrict__ src,
                                   const int* __restrict__ dst) {
    int e = blockIdx.x * blockDim.x + threadIdx.x;
    if (e >= N_EDGES) return;
    bool s64 = idx_is64(src);
    bool d64 = idx_is64(dst);
    int s = edge_idx(src, s64, e);
    int d = edge_idx(dst, d64, e);
    int pos = atomicAdd(&g_cursor[d], 1);
    g_ssrc[pos] = s;
    g_sw[pos] = ew[e];
}

// Warp-per-node gather, unroll-4; zeroes g_cnt after use (next-call hist)
__global__ void gather_kernel(const float* __restrict__ nf) {
    int w = (blockIdx.x * blockDim.x + threadIdx.x) >> 5;
    int lane = threadIdx.x & 31;
    if (w >= N_NODES) return;
    int beg = g_offs[w];
    int deg = g_cnt[w];
    const float4* nf4 = (const float4*)nf;
    float4 acc = make_float4(0.f, 0.f, 0.f, 0.f);

    int i = 0;
    for (; i + 4 <= deg; i += 4) {
        int   s0 = g_ssrc[beg + i];
        int   s1 = g_ssrc[beg + i + 1];
        int   s2 = g_ssrc[beg + i + 2];
        int   s3 = g_ssrc[beg + i + 3];
        float w0 = g_sw[beg + i];
        float w1 = g_sw[beg + i + 1];
        float w2 = g_sw[beg + i + 2];
        float w3 = g_sw[beg + i + 3];
        float4 v0 = nf4[s0 * (D / 4) + lane];
        float4 v1 = nf4[s1 * (D / 4) + lane];
        float4 v2 = nf4[s2 * (D / 4) + lane];
        float4 v3 = nf4[s3 * (D / 4) + lane];
        acc.x += v0.x * w0; acc.y += v0.y * w0; acc.z += v0.z * w0; acc.w += v0.w * w0;
        acc.x += v1.x * w1; acc.y += v1.y * w1; acc.z += v1.z * w1; acc.w += v1.w * w1;
        acc.x += v2.x * w2; acc.y += v2.y * w2; acc.z += v2.z * w2; acc.w += v2.w * w2;
        acc.x += v3.x * w3; acc.y += v3.y * w3; acc.z += v3.z * w3; acc.w += v3.w * w3;
    }
    for (; i < deg; i++) {
        int s = g_ssrc[beg + i];
        float wt = g_sw[beg + i];
        float4 v = nf4[s * (D / 4) + lane];
        acc.x += v.x * wt; acc.y += v.y * wt; acc.z += v.z * wt; acc.w += v.w * wt;
    }
    float inv = (deg > 0) ? (1.0f / (float)deg) : 0.0f;
    acc.x *= inv; acc.y *= inv; acc.z *= inv; acc.w *= inv;
    ((float4*)g_agg)[w * (D / 4) + lane] = acc;
    if (lane == 0) g_cnt[w] = 0;   // reset for next call's hist
}

// ---------------------------------------------------------------------------
// bf16-split MMA GEMM, GBM=128: each warp-pair covers 32 rows; every B
// fragment load feeds two m16n8 tiles; W traffic per kernel halves.
// ---------------------------------------------------------------------------
__device__ __forceinline__ void mma_bf16(float* c, const uint32_t* a,
                                         uint32_t b0, uint32_t b1) {
    asm volatile(
        "mma.sync.aligned.m16n8k16.row.col.f32.bf16.bf16.f32 "
        "{%0,%1,%2,%3}, {%4,%5,%6,%7}, {%8,%9}, {%0,%1,%2,%3};"
        : "+f"(c[0]), "+f"(c[1]), "+f"(c[2]), "+f"(c[3])
        : "r"(a[0]), "r"(a[1]), "r"(a[2]), "r"(a[3]), "r"(b0), "r"(b1));
}

__global__ __launch_bounds__(256, 2)
void gemm_bf16_kernel(const float* __restrict__ nf,
                      const float* __restrict__ bias,
                      float* __restrict__ out) {
    __shared__ __align__(16) uint32_t Ah[2][1024];   // 8 m-groups x 128 words
    __shared__ __align__(16) uint32_t Al[2][1024];
    __shared__ __align__(16) uint32_t Bh[2][4][264];
    __shared__ __align__(16) uint32_t Bl[2][4][264];

    int tx   = threadIdx.x;
    int w    = tx >> 5;
    int lane = tx & 31;
    int g    = lane >> 2;
    int tig  = lane & 3;
    int mwg  = w >> 1;            // 0..3: rows [32mwg, 32mwg+32)
    int nw   = (w & 1) * 64;
    int n0   = blockIdx.x * GBM;

    float c[2][8][4];
    #pragma unroll
    for (int mt = 0; mt < 2; mt++)
        #pragma unroll
        for (int t = 0; t < 8; t++)
            #pragma unroll
            for (int i = 0; i < 4; i++) c[mt][t][i] = 0.f;

    // A fill: 512 float4 per chunk, 2 per thread (r = 0,1)
    int am[2], aq[2], ad0[2], ad1[2], anode[2];
    #pragma unroll
    for (int r = 0; r < 2; r++) {
        int f4 = tx + r * 256;
        am[r] = f4 >> 2;
        aq[r] = f4 & 3;
        int an = n0 + am[r];
        anode[r] = (an < N_NODES) ? an : 0;
        int ar = am[r] & 15, ag = ar & 7, ahalf = ar >> 3, amg = am[r] >> 4;
        int i0 = 2 * aq[r], i1 = 2 * aq[r] + 1;
        ad0[r] = amg * 128 + (4 * ag + (i0 & 3)) * 4 + ahalf + 2 * (i0 >> 2);
        ad1[r] = amg * 128 + (4 * ag + (i1 & 3)) * 4 + ahalf + 2 * (i1 >> 2);
    }

    const uint2* Wh2 = (const uint2*)g_Wbh;
    const uint2* Wl2 = (const uint2*)g_Wbl;
    int t0row = tx >> 7;
    int t0off = (2 * tx) & 255;

    // prologue: chunk 0 -> buf 0
    #pragma unroll
    for (int r = 0; r < 2; r++) {
        float4 f = *(const float4*)(g_agg + (long long)anode[r] * D + aq[r] * 4);
        uint32_t h0, l0, h1, l1;
        splitpack2(f.x, f.y, h0, l0);
        splitpack2(f.z, f.w, h1, l1);
        Ah[0][ad0[r]] = h0; Al[0][ad0[r]] = l0;
        Ah[0][ad1[r]] = h1; Al[0][ad1[r]] = l1;
    }
    {
        uint2 bh0 = Wh2[tx], bh1 = Wh2[tx + 256];
        uint2 bl0 = Wl2[tx], bl1 = Wl2[tx + 256];
        *(uint2*)&Bh[0][t0row][t0off]     = bh0;
        *(uint2*)&Bh[0][t0row + 2][t0off] = bh1;
        *(uint2*)&Bl[0][t0row][t0off]     = bl0;
        *(uint2*)&Bl[0][t0row + 2][t0off] = bl1;
    }
    __syncthreads();

    for (int kt = 0; kt < NCHUNK; kt++) {
        int b = kt & 1;

        float4 pf[2];
        uint2 ph0, ph1, pl0, pl1;
        if (kt + 1 < NCHUNK) {
            int k0 = (kt + 1) * 16;
            const float* zb = (k0 < D) ? (g_agg + k0) : (nf + (k0 - D));
            #pragma unroll
            for (int r = 0; r < 2; r++)
                pf[r] = *(const float4*)(zb + (long long)anode[r] * D + aq[r] * 4);
            int cb = (kt + 1) * 512;
            ph0 = Wh2[cb + tx]; ph1 = Wh2[cb + tx + 256];
            pl0 = Wl2[cb + tx]; pl1 = Wl2[cb + tx + 256];
        }

        uint32_t ah[2][4], al[2][4];
        #pragma unroll
        for (int mt = 0; mt < 2; mt++) {
            uint4 h4 = *(const uint4*)&Ah[b][(2 * mwg + mt) * 128 + lane * 4];
            uint4 l4 = *(const uint4*)&Al[b][(2 * mwg + mt) * 128 + lane * 4];
            ah[mt][0] = h4.x; ah[mt][1] = h4.y; ah[mt][2] = h4.z; ah[mt][3] = h4.w;
            al[mt][0] = l4.x; al[mt][1] = l4.y; al[mt][2] = l4.z; al[mt][3] = l4.w;
        }
        #pragma unroll
        for (int t = 0; t < 8; t++) {
            int nn = nw + t * 8 + g;
            uint2 bh = *(const uint2*)&Bh[b][tig][nn * 2];
            uint2 bl = *(const uint2*)&Bl[b][tig][nn * 2];
            #pragma unroll
            for (int mt = 0; mt < 2; mt++) {
                mma_bf16(c[mt][t], ah[mt], bh.x, bh.y);
                mma_bf16(c[mt][t], al[mt], bh.x, bh.y);
                mma_bf16(c[mt][t], ah[mt], bl.x, bl.y);
            }
        }

        if (kt + 1 < NCHUNK) {
            int nb = b ^ 1;
            #pragma unroll
            for (int r = 0; r < 2; r++) {
                uint32_t h0, l0, h1, l1;
                splitpack2(pf[r].x, pf[r].y, h0, l0);
                splitpack2(pf[r].z, pf[r].w, h1, l1);
                Ah[nb][ad0[r]] = h0; Al[nb][ad0[r]] = l0;
                Ah[nb][ad1[r]] = h1; Al[nb][ad1[r]] = l1;
            }
            *(uint2*)&Bh[nb][t0row][t0off]     = ph0;
            *(uint2*)&Bh[nb][t0row + 2][t0off] = ph1;
            *(uint2*)&Bl[nb][t0row][t0off]     = pl0;
            *(uint2*)&Bl[nb][t0row + 2][t0off] = pl1;
        }
        __syncthreads();
    }

    // epilogue: bias + store
    #pragma unroll
    for (int mt = 0; mt < 2; mt++) {
        int r0 = n0 + mwg * 32 + mt * 16 + g;
        int r1 = r0 + 8;
        #pragma unroll
        for (int t = 0; t < 8; t++) {
            int col = nw + t * 8 + 2 * tig;
            float2 bv = *(const float2*)(bias + col);
            if (r0 < N_NODES) {
                float2 o0 = make_float2(c[mt][t][0] + bv.x, c[mt][t][1] + bv.y);
                *(float2*)(out + (long long)r0 * GBN + col) = o0;
            }
            if (r1 < N_NODES) {
                float2 o1 = make_float2(c[mt][t][2] + bv.x, c[mt][t][3] + bv.y);
                *(float2*)(out + (long long)r1 * GBN + col) = o1;
            }
        }
    }
}

// ---------------------------------------------------------------------------
extern "C" void kernel_launch(void* const* d_in, const int* in_sizes, int n_in,
                              void* d_out, int out_size) {
    const float* nf   = (const float*)d_in[0];
    const float* ew   = (const float*)d_in[1];
    const float* W    = (const float*)d_in[2];
    const float* bias = (const float*)d_in[3];
    const int* src    = (const int*)d_in[4];
    const int* dst    = (const int*)d_in[5];
    float* out        = (float*)d_out;

    hist_init_kernel<<<(N_EDGES + 255) / 256, 256>>>(W, dst);
    scan_pass1<<<SCAN_NB, SCAN_BT>>>();
    scan_pass23<<<SCAN_NB, SCAN_BT>>>();
    scatter_ids_kernel<<<(N_EDGES + 255) / 256, 256>>>(ew, src, dst);
    gather_kernel<<<(N_NODES * 32 + 255) / 256, 256>>>(nf);
    gemm_bf16_kernel<<<(N_NODES + GBM - 1) / GBM, 256>>>(nf, bias, out);
}